// round 9
// baseline (speedup 1.0000x reference)
#include <cuda_runtime.h>
#include <cuda_bf16.h>
#include <math.h>
#include <stdint.h>

// Problem constants (Origin_HyperKA): N=100000, D=128, E=800000, L=2
#define ND 128
#define MAXN 100000
#define PMAX 0.99999f      /* 1 - PROJ_EPS */
#define MINN 1e-15f        /* MIN_NORM */

// Scratch (allocation-free rule: __device__ globals)
__device__ float g_x[MAXN * ND];    // current layer input x (projected)
__device__ float g_m[MAXN * ND];    // m = logmap(x) @ W_l
__device__ float g_agg[MAXN * ND];  // segment-sum accumulator

// ---------------------------------------------------------------- utilities
__device__ __forceinline__ float warp_sum(float v) {
    v += __shfl_xor_sync(0xffffffffu, v, 16);
    v += __shfl_xor_sync(0xffffffffu, v, 8);
    v += __shfl_xor_sync(0xffffffffu, v, 4);
    v += __shfl_xor_sync(0xffffffffu, v, 2);
    v += __shfl_xor_sync(0xffffffffu, v, 1);
    return v;
}
__device__ __forceinline__ float dot4(float4 a, float4 b) {
    return a.x * b.x + a.y * b.y + a.z * b.z + a.w * b.w;
}
__device__ __forceinline__ float4 scale4(float4 a, float s) {
    return make_float4(a.x * s, a.y * s, a.z * s, a.w * s);
}
// hyperbolic_projection (warp-collective over one row)
__device__ __forceinline__ float4 proj4(float4 v) {
    float n = sqrtf(warp_sum(dot4(v, v)));
    if (n > PMAX) v = scale4(v, PMAX / fmaxf(n, MINN));
    return v;
}
// exp_map_zero
__device__ __forceinline__ float4 expmap4(float4 v) {
    float n = sqrtf(warp_sum(dot4(v, v)));
    float nm = fmaxf(n, MINN);
    return scale4(v, tanhf(nm) / nm);
}
// log_map_zero
__device__ __forceinline__ float4 logmap4(float4 v) {
    float n = sqrtf(warp_sum(dot4(v, v)));
    float nm = fmaxf(n, MINN);
    float nc = fminf(nm, PMAX);
    return scale4(v, atanhf(nc) / nm);
}
// mobius_addition(u, v)
__device__ __forceinline__ float4 mobius4(float4 u, float4 v) {
    float uu = warp_sum(dot4(u, u));
    float vv = warp_sum(dot4(v, v));
    float uv = warp_sum(dot4(u, v));
    float cu = 1.0f + 2.0f * uv + vv;
    float cv = 1.0f - uu;
    float den = fmaxf(1.0f + 2.0f * uv + uu * vv, MINN);
    float inv = 1.0f / den;
    return make_float4((cu * u.x + cv * v.x) * inv, (cu * u.y + cv * v.y) * inv,
                       (cu * u.z + cv * v.z) * inv, (cu * u.w + cv * v.w) * inv);
}

// ---------------------------------------------------------------- kernels
// bf16 m16n8k16 mma wrapper
__device__ __forceinline__ void mma16816(float* d, const unsigned* a, const unsigned* b) {
    asm volatile(
        "mma.sync.aligned.m16n8k16.row.col.f32.bf16.bf16.f32 "
        "{%0,%1,%2,%3}, {%4,%5,%6,%7}, {%8,%9}, {%0,%1,%2,%3};\n"
        : "+f"(d[0]), "+f"(d[1]), "+f"(d[2]), "+f"(d[3])
        : "r"(a[0]), "r"(a[1]), "r"(a[2]), "r"(a[3]), "r"(b[0]), "r"(b[1]));
}
__device__ __forceinline__ unsigned pack_bf2(__nv_bfloat16 lo, __nv_bfloat16 hi) {
    unsigned l = (unsigned)__bfloat16_as_ushort(lo);
    unsigned h = (unsigned)__bfloat16_as_ushort(hi);
    return l | (h << 16);
}

// Fused: [optional x=proj(in)] ; t = log_map_zero(x) ; m = t @ W
// Per block: 128 rows, full K=N=128. Also zeroes this block's agg rows.
// bf16 split GEMM: m = t_hi*W_hi + t_lo*W_hi + t_hi*W_lo  (err ~2^-16)
#define AS 136  // smem row stride in bf16 elements (conflict-free for A/B access)
__global__ __launch_bounds__(256, 1) void gemm_logmap_kernel(
    const float* __restrict__ Xin, const float* __restrict__ Wg,
    float* __restrict__ Mout, float* __restrict__ Agg,
    float* __restrict__ Xproj, int nrows, int do_proj) {
    extern __shared__ unsigned char dynsmem[];
    __nv_bfloat16* sAh = (__nv_bfloat16*)dynsmem;            // [128][AS] t_hi
    __nv_bfloat16* sAl = sAh + 128 * AS;                     // t_lo
    __nv_bfloat16* sBh = sAl + 128 * AS;                     // W_hi  [k][n]
    __nv_bfloat16* sBl = sBh + 128 * AS;                     // W_lo

    int tid = threadIdx.x, lane = tid & 31, warp = tid >> 5;
    size_t row0 = (size_t)blockIdx.x * 128;

    // --- load rows, [proj], apply log_map_zero, split to bf16 hi/lo; zero agg
    const float4 z4 = make_float4(0.f, 0.f, 0.f, 0.f);
    for (int rr = 0; rr < 16; ++rr) {
        int r = warp * 16 + rr;
        size_t gr = row0 + r;
        float4 v = z4;
        if (gr < (size_t)nrows) {
            v = *(const float4*)(Xin + gr * ND + lane * 4);
            *(float4*)(Agg + gr * ND + lane * 4) = z4;   // zero accumulator row
        }
        if (do_proj) {
            v = proj4(v);
            if (gr < (size_t)nrows)
                *(float4*)(Xproj + gr * ND + lane * 4) = v;  // x for residual
        }
        float n = sqrtf(warp_sum(dot4(v, v)));
        float nm = fmaxf(n, MINN);
        float nc = fminf(nm, PMAX);
        float sc = atanhf(nc) / nm;
        float t[4] = {v.x * sc, v.y * sc, v.z * sc, v.w * sc};
#pragma unroll
        for (int j = 0; j < 4; ++j) {
            __nv_bfloat16 hi = __float2bfloat16(t[j]);
            __nv_bfloat16 lo = __float2bfloat16(t[j] - __bfloat162float(hi));
            sAh[r * AS + lane * 4 + j] = hi;
            sAl[r * AS + lane * 4 + j] = lo;
        }
    }
    // --- load W (natural [k][n] layout), split hi/lo
    for (int i = tid; i < ND * ND / 4; i += 256) {
        int k = i >> 5;
        int j = (i & 31) * 4;
        float4 w = ((const float4*)Wg)[i];
        float wv[4] = {w.x, w.y, w.z, w.w};
#pragma unroll
        for (int jj = 0; jj < 4; ++jj) {
            __nv_bfloat16 hi = __float2bfloat16(wv[jj]);
            sBh[k * AS + j + jj] = hi;
            sBl[k * AS + j + jj] = __float2bfloat16(wv[jj] - __bfloat162float(hi));
        }
    }
    __syncthreads();

    // --- warp tiling: 8 warps as 4(M) x 2(N); warp tile 32x64
    int wm = warp & 3, wn = warp >> 2;
    int g = lane >> 2, tg = lane & 3;
    float acc[2][8][4];
#pragma unroll
    for (int f = 0; f < 2; ++f)
#pragma unroll
        for (int nf = 0; nf < 8; ++nf)
#pragma unroll
            for (int q = 0; q < 4; ++q) acc[f][nf][q] = 0.f;

    for (int kb = 0; kb < 128; kb += 16) {
        unsigned ah[2][4], al[2][4];
#pragma unroll
        for (int f = 0; f < 2; ++f) {
            int r = wm * 32 + f * 16 + g;
            int c = kb + tg * 2;
            ah[f][0] = *(const unsigned*)&sAh[r * AS + c];
            ah[f][1] = *(const unsigned*)&sAh[(r + 8) * AS + c];
            ah[f][2] = *(const unsigned*)&sAh[r * AS + c + 8];
            ah[f][3] = *(const unsigned*)&sAh[(r + 8) * AS + c + 8];
            al[f][0] = *(const unsigned*)&sAl[r * AS + c];
            al[f][1] = *(const unsigned*)&sAl[(r + 8) * AS + c];
            al[f][2] = *(const unsigned*)&sAl[r * AS + c + 8];
            al[f][3] = *(const unsigned*)&sAl[(r + 8) * AS + c + 8];
        }
        unsigned bh[8][2], bl[8][2];
#pragma unroll
        for (int nf = 0; nf < 8; ++nf) {
            int n = wn * 64 + nf * 8 + g;
            int k0 = kb + tg * 2;
            bh[nf][0] = pack_bf2(sBh[k0 * AS + n], sBh[(k0 + 1) * AS + n]);
            bh[nf][1] = pack_bf2(sBh[(k0 + 8) * AS + n], sBh[(k0 + 9) * AS + n]);
            bl[nf][0] = pack_bf2(sBl[k0 * AS + n], sBl[(k0 + 1) * AS + n]);
            bl[nf][1] = pack_bf2(sBl[(k0 + 8) * AS + n], sBl[(k0 + 9) * AS + n]);
        }
#pragma unroll
        for (int f = 0; f < 2; ++f)
#pragma unroll
            for (int nf = 0; nf < 8; ++nf) {
                mma16816(acc[f][nf], ah[f], bh[nf]);  // hi*Whi
                mma16816(acc[f][nf], al[f], bh[nf]);  // lo*Whi
                mma16816(acc[f][nf], ah[f], bl[nf]);  // hi*Wlo
            }
    }

    // --- store m
#pragma unroll
    for (int f = 0; f < 2; ++f) {
        size_t r = row0 + wm * 32 + f * 16 + g;
#pragma unroll
        for (int nf = 0; nf < 8; ++nf) {
            int cc = wn * 64 + nf * 8 + tg * 2;
            if (r < (size_t)nrows)
                *(float2*)&Mout[r * ND + cc] = make_float2(acc[f][nf][0], acc[f][nf][1]);
            if (r + 8 < (size_t)nrows)
                *(float2*)&Mout[(r + 8) * ND + cc] = make_float2(acc[f][nf][2], acc[f][nf][3]);
        }
    }
}

// agg[rows[e]] += m[cols[e]] * vals[e]; one warp per edge, grid-stride,
// 2-deep unroll for gather MLP; vector f32 L2 reductions
__global__ __launch_bounds__(256) void scatter_kernel(
    const float* __restrict__ M, const int* __restrict__ rows,
    const int* __restrict__ cols, const float* __restrict__ vals,
    float* __restrict__ agg, int E) {
    int lane = threadIdx.x & 31;
    int w0 = (blockIdx.x * blockDim.x + threadIdx.x) >> 5;
    int wstride = (gridDim.x * blockDim.x) >> 5;
    int w = w0;
    for (; w + wstride < E; w += 2 * wstride) {
        int w1 = w + wstride;
        int r0 = __ldg(rows + w),  c0 = __ldg(cols + w);
        int r1 = __ldg(rows + w1), c1 = __ldg(cols + w1);
        float v0 = __ldg(vals + w), v1 = __ldg(vals + w1);
        float4 d0 = *(const float4*)(M + (size_t)c0 * ND + lane * 4);
        float4 d1 = *(const float4*)(M + (size_t)c1 * ND + lane * 4);
        d0.x *= v0; d0.y *= v0; d0.z *= v0; d0.w *= v0;
        d1.x *= v1; d1.y *= v1; d1.z *= v1; d1.w *= v1;
        float* p0 = agg + (size_t)r0 * ND + lane * 4;
        float* p1 = agg + (size_t)r1 * ND + lane * 4;
        asm volatile("red.global.add.v4.f32 [%0], {%1,%2,%3,%4};"
                     :: "l"(p0), "f"(d0.x), "f"(d0.y), "f"(d0.z), "f"(d0.w)
                     : "memory");
        asm volatile("red.global.add.v4.f32 [%0], {%1,%2,%3,%4};"
                     :: "l"(p1), "f"(d1.x), "f"(d1.y), "f"(d1.z), "f"(d1.w)
                     : "memory");
    }
    if (w < E) {
        int r = __ldg(rows + w);
        int c = __ldg(cols + w);
        float v = __ldg(vals + w);
        float4 d = *(const float4*)(M + (size_t)c * ND + lane * 4);
        d.x *= v; d.y *= v; d.z *= v; d.w *= v;
        float* dst = agg + (size_t)r * ND + lane * 4;
        asm volatile("red.global.add.v4.f32 [%0], {%1,%2,%3,%4};"
                     :: "l"(dst), "f"(d.x), "f"(d.y), "f"(d.z), "f"(d.w)
                     : "memory");
    }
}

// h = proj(exp(agg)); h = proj(mobius(h, proj(exp(bias)))); [act]; out = proj(mobius(h, x))
__global__ __launch_bounds__(512) void post_kernel(
    const float* __restrict__ agg, const float* __restrict__ xold,
    const float* __restrict__ bias, float* __restrict__ out, int nrows, int act) {
    int w = (blockIdx.x * blockDim.x + threadIdx.x) >> 5;
    if (w >= nrows) return;
    int lane = threadIdx.x & 31;
    size_t off = (size_t)w * ND + lane * 4;
    float4 a = *(const float4*)(agg + off);
    float4 xo = *(const float4*)(xold + off);
    float4 b = *(const float4*)(bias + lane * 4);

    float4 h = proj4(expmap4(a));
    float4 bh = proj4(expmap4(b));
    h = proj4(mobius4(h, bh));
    if (act) {
        float4 t = logmap4(h);
        t.x = tanhf(t.x); t.y = tanhf(t.y); t.z = tanhf(t.z); t.w = tanhf(t.w);
        h = proj4(expmap4(t));
    }
    h = proj4(mobius4(h, xo));
    *(float4*)(out + off) = h;
}

// ---------------------------------------------------------------- launch
extern "C" void kernel_launch(void* const* d_in, const int* in_sizes, int n_in,
                              void* d_out, int out_size) {
    const float* ent  = (const float*)d_in[0];
    const float* W    = (const float*)d_in[1];
    const float* bias = (const float*)d_in[2];
    const int* rows   = (const int*)d_in[3];
    const int* cols   = (const int*)d_in[4];
    const float* vals = (const float*)d_in[5];
    float* out = (float*)d_out;

    const int N_ = in_sizes[0] / ND;               // 100000
    const int L_ = in_sizes[1] / (ND * ND);        // 2
    const int E_ = in_sizes[3];                    // 800000

    float *px, *pm, *pagg;
    cudaGetSymbolAddress((void**)&px, g_x);
    cudaGetSymbolAddress((void**)&pm, g_m);
    cudaGetSymbolAddress((void**)&pagg, g_agg);

    const int SMEMSZ = 4 * 128 * AS * (int)sizeof(__nv_bfloat16);
    cudaFuncSetAttribute(gemm_logmap_kernel,
                         cudaFuncAttributeMaxDynamicSharedMemorySize, SMEMSZ);

    // scatter grid: full-occupancy slots, grid-stride over E (unroll x2 inside)
    int sc_blocks = 148 * 4;   // 4 blocks/SM x 8 warps = 32 warps/SM
    int sc_needed = (E_ + 15) / 16;
    if (sc_blocks > sc_needed) sc_blocks = sc_needed;
    if (sc_blocks < 1) sc_blocks = 1;

    for (int l = 0; l < L_; ++l) {
        // layer 0: input = ent, fused proj writes px; later layers read px
        gemm_logmap_kernel<<<(N_ + 127) / 128, 256, SMEMSZ>>>(
            (l == 0) ? ent : px, W + (size_t)l * ND * ND, pm, pagg, px, N_,
            (l == 0) ? 1 : 0);
        scatter_kernel<<<sc_blocks, 256>>>(pm, rows, cols, vals, pagg, E_);
        post_kernel<<<(N_ + 15) / 16, 512>>>(
            pagg, px, bias + (size_t)l * ND, (l == L_ - 1) ? out : px, N_,
            (l < L_ - 1) ? 1 : 0);
    }
}

// round 13
// speedup vs baseline: 1.1585x; 1.1585x over previous
#include <cuda_runtime.h>
#include <cuda_bf16.h>
#include <math.h>
#include <stdint.h>

// Problem constants (Origin_HyperKA): N=100000, D=128, E=800000, L=2
#define ND 128
#define MAXN 100000
#define PMAX 0.99999f      /* 1 - PROJ_EPS */
#define MINN 1e-15f        /* MIN_NORM */

// Scratch (allocation-free rule: __device__ globals)
__device__ float g_x[MAXN * ND];    // current layer input x (projected)
__device__ float g_m[MAXN * ND];    // m = logmap(x) @ W_l
__device__ float g_agg[MAXN * ND];  // segment-sum accumulator

// ---------------------------------------------------------------- utilities
__device__ __forceinline__ float warp_sum(float v) {
    v += __shfl_xor_sync(0xffffffffu, v, 16);
    v += __shfl_xor_sync(0xffffffffu, v, 8);
    v += __shfl_xor_sync(0xffffffffu, v, 4);
    v += __shfl_xor_sync(0xffffffffu, v, 2);
    v += __shfl_xor_sync(0xffffffffu, v, 1);
    return v;
}
__device__ __forceinline__ float dot4(float4 a, float4 b) {
    return a.x * b.x + a.y * b.y + a.z * b.z + a.w * b.w;
}
__device__ __forceinline__ float4 scale4(float4 a, float s) {
    return make_float4(a.x * s, a.y * s, a.z * s, a.w * s);
}
// hyperbolic_projection (warp-collective over one row)
__device__ __forceinline__ float4 proj4(float4 v) {
    float n = sqrtf(warp_sum(dot4(v, v)));
    if (n > PMAX) v = scale4(v, PMAX / fmaxf(n, MINN));
    return v;
}
// exp_map_zero
__device__ __forceinline__ float4 expmap4(float4 v) {
    float n = sqrtf(warp_sum(dot4(v, v)));
    float nm = fmaxf(n, MINN);
    return scale4(v, tanhf(nm) / nm);
}
// log_map_zero
__device__ __forceinline__ float4 logmap4(float4 v) {
    float n = sqrtf(warp_sum(dot4(v, v)));
    float nm = fmaxf(n, MINN);
    float nc = fminf(nm, PMAX);
    return scale4(v, atanhf(nc) / nm);
}
// mobius_addition(u, v)
__device__ __forceinline__ float4 mobius4(float4 u, float4 v) {
    float uu = warp_sum(dot4(u, u));
    float vv = warp_sum(dot4(v, v));
    float uv = warp_sum(dot4(u, v));
    float cu = 1.0f + 2.0f * uv + vv;
    float cv = 1.0f - uu;
    float den = fmaxf(1.0f + 2.0f * uv + uu * vv, MINN);
    float inv = 1.0f / den;
    return make_float4((cu * u.x + cv * v.x) * inv, (cu * u.y + cv * v.y) * inv,
                       (cu * u.z + cv * v.z) * inv, (cu * u.w + cv * v.w) * inv);
}

// ---------------------------------------------------------------- kernels
// bf16 m16n8k16 mma wrapper
__device__ __forceinline__ void mma16816(float* d, const unsigned* a, const unsigned* b) {
    asm volatile(
        "mma.sync.aligned.m16n8k16.row.col.f32.bf16.bf16.f32 "
        "{%0,%1,%2,%3}, {%4,%5,%6,%7}, {%8,%9}, {%0,%1,%2,%3};\n"
        : "+f"(d[0]), "+f"(d[1]), "+f"(d[2]), "+f"(d[3])
        : "r"(a[0]), "r"(a[1]), "r"(a[2]), "r"(a[3]), "r"(b[0]), "r"(b[1]));
}
__device__ __forceinline__ unsigned pack_bf2(__nv_bfloat16 lo, __nv_bfloat16 hi) {
    unsigned l = (unsigned)__bfloat16_as_ushort(lo);
    unsigned h = (unsigned)__bfloat16_as_ushort(hi);
    return l | (h << 16);
}

// Fused: [optional x=proj(in)] ; t = log_map_zero(x) ; m = t @ W
// Per block: 128 rows, full K=N=128. Also zeroes this block's agg rows.
// 512 threads (16 warps, 4x4 warp grid, 32x32 warp tiles) for latency hiding.
// bf16 split GEMM: m = t_hi*W_hi + t_lo*W_hi + t_hi*W_lo  (err ~2^-16)
#define AS 136  // smem row stride in bf16 elements (conflict-free for A/B access)
__global__ __launch_bounds__(512, 1) void gemm_logmap_kernel(
    const float* __restrict__ Xin, const float* __restrict__ Wg,
    float* __restrict__ Mout, float* __restrict__ Agg,
    float* __restrict__ Xproj, int nrows, int do_proj) {
    extern __shared__ unsigned char dynsmem[];
    __nv_bfloat16* sAh = (__nv_bfloat16*)dynsmem;            // [128][AS] t_hi
    __nv_bfloat16* sAl = sAh + 128 * AS;                     // t_lo
    __nv_bfloat16* sBh = sAl + 128 * AS;                     // W_hi  [k][n]
    __nv_bfloat16* sBl = sBh + 128 * AS;                     // W_lo

    int tid = threadIdx.x, lane = tid & 31, warp = tid >> 5;  // 16 warps
    size_t row0 = (size_t)blockIdx.x * 128;

    // --- load rows (8 per warp), [proj], logmap, split bf16 hi/lo; zero agg
    const float4 z4 = make_float4(0.f, 0.f, 0.f, 0.f);
    for (int rr = 0; rr < 8; ++rr) {
        int r = warp * 8 + rr;
        size_t gr = row0 + r;
        float4 v = z4;
        if (gr < (size_t)nrows) {
            v = *(const float4*)(Xin + gr * ND + lane * 4);
            *(float4*)(Agg + gr * ND + lane * 4) = z4;   // zero accumulator row
        }
        if (do_proj) {
            v = proj4(v);
            if (gr < (size_t)nrows)
                *(float4*)(Xproj + gr * ND + lane * 4) = v;  // x for residual
        }
        float n = sqrtf(warp_sum(dot4(v, v)));
        float nm = fmaxf(n, MINN);
        float nc = fminf(nm, PMAX);
        float sc = atanhf(nc) / nm;
        float t[4] = {v.x * sc, v.y * sc, v.z * sc, v.w * sc};
#pragma unroll
        for (int j = 0; j < 4; ++j) {
            __nv_bfloat16 hi = __float2bfloat16(t[j]);
            __nv_bfloat16 lo = __float2bfloat16(t[j] - __bfloat162float(hi));
            sAh[r * AS + lane * 4 + j] = hi;
            sAl[r * AS + lane * 4 + j] = lo;
        }
    }
    // --- load W (natural [k][n] layout), split hi/lo
    for (int i = tid; i < ND * ND / 4; i += 512) {
        int k = i >> 5;
        int j = (i & 31) * 4;
        float4 w = ((const float4*)Wg)[i];
        float wv[4] = {w.x, w.y, w.z, w.w};
#pragma unroll
        for (int jj = 0; jj < 4; ++jj) {
            __nv_bfloat16 hi = __float2bfloat16(wv[jj]);
            sBh[k * AS + j + jj] = hi;
            sBl[k * AS + j + jj] = __float2bfloat16(wv[jj] - __bfloat162float(hi));
        }
    }
    __syncthreads();

    // --- warp tiling: 16 warps as 4(M) x 4(N); warp tile 32x32
    int wm = warp & 3, wn = warp >> 2;
    int g = lane >> 2, tg = lane & 3;
    float acc[2][4][4];
#pragma unroll
    for (int f = 0; f < 2; ++f)
#pragma unroll
        for (int nf = 0; nf < 4; ++nf)
#pragma unroll
            for (int q = 0; q < 4; ++q) acc[f][nf][q] = 0.f;

    for (int kb = 0; kb < 128; kb += 16) {
        unsigned ah[2][4], al[2][4];
#pragma unroll
        for (int f = 0; f < 2; ++f) {
            int r = wm * 32 + f * 16 + g;
            int c = kb + tg * 2;
            ah[f][0] = *(const unsigned*)&sAh[r * AS + c];
            ah[f][1] = *(const unsigned*)&sAh[(r + 8) * AS + c];
            ah[f][2] = *(const unsigned*)&sAh[r * AS + c + 8];
            ah[f][3] = *(const unsigned*)&sAh[(r + 8) * AS + c + 8];
            al[f][0] = *(const unsigned*)&sAl[r * AS + c];
            al[f][1] = *(const unsigned*)&sAl[(r + 8) * AS + c];
            al[f][2] = *(const unsigned*)&sAl[r * AS + c + 8];
            al[f][3] = *(const unsigned*)&sAl[(r + 8) * AS + c + 8];
        }
        unsigned bh[4][2], bl[4][2];
#pragma unroll
        for (int nf = 0; nf < 4; ++nf) {
            int n = wn * 32 + nf * 8 + g;
            int k0 = kb + tg * 2;
            bh[nf][0] = pack_bf2(sBh[k0 * AS + n], sBh[(k0 + 1) * AS + n]);
            bh[nf][1] = pack_bf2(sBh[(k0 + 8) * AS + n], sBh[(k0 + 9) * AS + n]);
            bl[nf][0] = pack_bf2(sBl[k0 * AS + n], sBl[(k0 + 1) * AS + n]);
            bl[nf][1] = pack_bf2(sBl[(k0 + 8) * AS + n], sBl[(k0 + 9) * AS + n]);
        }
#pragma unroll
        for (int f = 0; f < 2; ++f)
#pragma unroll
            for (int nf = 0; nf < 4; ++nf) {
                mma16816(acc[f][nf], ah[f], bh[nf]);  // hi*Whi
                mma16816(acc[f][nf], al[f], bh[nf]);  // lo*Whi
                mma16816(acc[f][nf], ah[f], bl[nf]);  // hi*Wlo
            }
    }

    // --- store m
#pragma unroll
    for (int f = 0; f < 2; ++f) {
        size_t r = row0 + wm * 32 + f * 16 + g;
#pragma unroll
        for (int nf = 0; nf < 4; ++nf) {
            int cc = wn * 32 + nf * 8 + tg * 2;
            if (r < (size_t)nrows)
                *(float2*)&Mout[r * ND + cc] = make_float2(acc[f][nf][0], acc[f][nf][1]);
            if (r + 8 < (size_t)nrows)
                *(float2*)&Mout[(r + 8) * ND + cc] = make_float2(acc[f][nf][2], acc[f][nf][3]);
        }
    }
}

// agg[rows[e]] += m[cols[e]] * vals[e]; one warp per edge, grid-stride,
// 4-deep unroll for gather MLP; vector f32 L2 reductions
__global__ __launch_bounds__(256) void scatter_kernel(
    const float* __restrict__ M, const int* __restrict__ rows,
    const int* __restrict__ cols, const float* __restrict__ vals,
    float* __restrict__ agg, int E) {
    int lane = threadIdx.x & 31;
    int w0 = (blockIdx.x * blockDim.x + threadIdx.x) >> 5;
    int wstride = (gridDim.x * blockDim.x) >> 5;
    int w = w0;
    for (; w + 3 * wstride < E; w += 4 * wstride) {
        int wa = w, wb = w + wstride, wc = w + 2 * wstride, wd = w + 3 * wstride;
        int ra = __ldg(rows + wa), ca = __ldg(cols + wa);
        int rb = __ldg(rows + wb), cb = __ldg(cols + wb);
        int rc = __ldg(rows + wc), cc = __ldg(cols + wc);
        int rd = __ldg(rows + wd), cd = __ldg(cols + wd);
        float va = __ldg(vals + wa), vb = __ldg(vals + wb);
        float vc = __ldg(vals + wc), vd = __ldg(vals + wd);
        float4 da = *(const float4*)(M + (size_t)ca * ND + lane * 4);
        float4 db = *(const float4*)(M + (size_t)cb * ND + lane * 4);
        float4 dc = *(const float4*)(M + (size_t)cc * ND + lane * 4);
        float4 dd = *(const float4*)(M + (size_t)cd * ND + lane * 4);
        da.x *= va; da.y *= va; da.z *= va; da.w *= va;
        db.x *= vb; db.y *= vb; db.z *= vb; db.w *= vb;
        dc.x *= vc; dc.y *= vc; dc.z *= vc; dc.w *= vc;
        dd.x *= vd; dd.y *= vd; dd.z *= vd; dd.w *= vd;
        float* pa = agg + (size_t)ra * ND + lane * 4;
        float* pb = agg + (size_t)rb * ND + lane * 4;
        float* pc = agg + (size_t)rc * ND + lane * 4;
        float* pd = agg + (size_t)rd * ND + lane * 4;
        asm volatile("red.global.add.v4.f32 [%0], {%1,%2,%3,%4};"
                     :: "l"(pa), "f"(da.x), "f"(da.y), "f"(da.z), "f"(da.w) : "memory");
        asm volatile("red.global.add.v4.f32 [%0], {%1,%2,%3,%4};"
                     :: "l"(pb), "f"(db.x), "f"(db.y), "f"(db.z), "f"(db.w) : "memory");
        asm volatile("red.global.add.v4.f32 [%0], {%1,%2,%3,%4};"
                     :: "l"(pc), "f"(dc.x), "f"(dc.y), "f"(dc.z), "f"(dc.w) : "memory");
        asm volatile("red.global.add.v4.f32 [%0], {%1,%2,%3,%4};"
                     :: "l"(pd), "f"(dd.x), "f"(dd.y), "f"(dd.z), "f"(dd.w) : "memory");
    }
    for (; w < E; w += wstride) {
        int r = __ldg(rows + w);
        int c = __ldg(cols + w);
        float v = __ldg(vals + w);
        float4 d = *(const float4*)(M + (size_t)c * ND + lane * 4);
        d.x *= v; d.y *= v; d.z *= v; d.w *= v;
        float* dst = agg + (size_t)r * ND + lane * 4;
        asm volatile("red.global.add.v4.f32 [%0], {%1,%2,%3,%4};"
                     :: "l"(dst), "f"(d.x), "f"(d.y), "f"(d.z), "f"(d.w)
                     : "memory");
    }
}

// h = proj(exp(agg)); h = proj(mobius(h, proj(exp(bias)))); [act]; out = proj(mobius(h, x))
__global__ __launch_bounds__(512) void post_kernel(
    const float* __restrict__ agg, const float* __restrict__ xold,
    const float* __restrict__ bias, float* __restrict__ out, int nrows, int act) {
    int w = (blockIdx.x * blockDim.x + threadIdx.x) >> 5;
    if (w >= nrows) return;
    int lane = threadIdx.x & 31;
    size_t off = (size_t)w * ND + lane * 4;
    float4 a = *(const float4*)(agg + off);
    float4 xo = *(const float4*)(xold + off);
    float4 b = *(const float4*)(bias + lane * 4);

    float4 h = proj4(expmap4(a));
    float4 bh = proj4(expmap4(b));
    h = proj4(mobius4(h, bh));
    if (act) {
        float4 t = logmap4(h);
        t.x = tanhf(t.x); t.y = tanhf(t.y); t.z = tanhf(t.z); t.w = tanhf(t.w);
        h = proj4(expmap4(t));
    }
    h = proj4(mobius4(h, xo));
    *(float4*)(out + off) = h;
}

// ---------------------------------------------------------------- launch
extern "C" void kernel_launch(void* const* d_in, const int* in_sizes, int n_in,
                              void* d_out, int out_size) {
    const float* ent  = (const float*)d_in[0];
    const float* W    = (const float*)d_in[1];
    const float* bias = (const float*)d_in[2];
    const int* rows   = (const int*)d_in[3];
    const int* cols   = (const int*)d_in[4];
    const float* vals = (const float*)d_in[5];
    float* out = (float*)d_out;

    const int N_ = in_sizes[0] / ND;               // 100000
    const int L_ = in_sizes[1] / (ND * ND);        // 2
    const int E_ = in_sizes[3];                    // 800000

    float *px, *pm, *pagg;
    cudaGetSymbolAddress((void**)&px, g_x);
    cudaGetSymbolAddress((void**)&pm, g_m);
    cudaGetSymbolAddress((void**)&pagg, g_agg);

    const int SMEMSZ = 4 * 128 * AS * (int)sizeof(__nv_bfloat16);
    cudaFuncSetAttribute(gemm_logmap_kernel,
                         cudaFuncAttributeMaxDynamicSharedMemorySize, SMEMSZ);

    // scatter grid: full-occupancy slots, grid-stride over E (unroll x4 inside)
    int sc_blocks = 148 * 4;   // 4 blocks/SM x 8 warps = 32 warps/SM
    int sc_needed = (E_ + 31) / 32;
    if (sc_blocks > sc_needed) sc_blocks = sc_needed;
    if (sc_blocks < 1) sc_blocks = 1;

    for (int l = 0; l < L_; ++l) {
        // layer 0: input = ent, fused proj writes px; later layers read px
        gemm_logmap_kernel<<<(N_ + 127) / 128, 512, SMEMSZ>>>(
            (l == 0) ? ent : px, W + (size_t)l * ND * ND, pm, pagg, px, N_,
            (l == 0) ? 1 : 0);
        scatter_kernel<<<sc_blocks, 256>>>(pm, rows, cols, vals, pagg, E_);
        post_kernel<<<(N_ + 15) / 16, 512>>>(
            pagg, px, bias + (size_t)l * ND, (l == L_ - 1) ? out : px, N_,
            (l < L_ - 1) ? 1 : 0);
    }
}